// round 1
// baseline (speedup 1.0000x reference)
#include <cuda_runtime.h>

// V-trace: all clip constants are 1.0 => rhos == cs == pg-clip.
// pg_advantages[i] == ys[i] (the reverse scan output), critic_loss == mean(ys^2).
// Single-pass reverse segmented scan with decoupled lookback.

#define BT 256
#define IT 16
#define TILE (BT * IT)
#define MAXTILES 4096

__device__ int   g_ticket;
__device__ int   g_flags[MAXTILES];     // 0 = invalid, 1 = aggregate, 2 = prefix
__device__ float g_aggA[MAXTILES];
__device__ float g_aggB[MAXTILES];
__device__ float g_preA[MAXTILES];
__device__ float g_preB[MAXTILES];
__device__ float g_partial[MAXTILES];   // per-tile sum of y^2

__global__ void vtrace_init(int ntiles) {
    int i = blockIdx.x * blockDim.x + threadIdx.x;
    if (i == 0) g_ticket = 0;
    if (i < ntiles) g_flags[i] = 0;
}

__global__ __launch_bounds__(BT) void vtrace_scan(
    const float* __restrict__ lp,  const float* __restrict__ olp,
    const float* __restrict__ val, const float* __restrict__ nval,
    const float* __restrict__ rew, const float* __restrict__ term,
    float* __restrict__ out_pg, int n, int ntiles)
{
    __shared__ int   s_tile;
    __shared__ float sA[BT], sB[BT];
    __shared__ float s_yR;

    if (threadIdx.x == 0) s_tile = atomicAdd(&g_ticket, 1);
    __syncthreads();
    const int t = s_tile;                 // t = 0 is the RIGHTMOST tile
    const int tid = threadIdx.x;
    const int j = BT - 1 - tid;           // j = 0 is the rightmost thread segment

    const long long base = (long long)n - (long long)(t + 1) * TILE;
    const long long ib = base + (long long)tid * IT;  // first (leftmost) item of this thread

    float a[IT], d[IT];
    const bool full = (ib >= 0) && (ib + IT <= (long long)n);

    if (full) {
        #pragma unroll
        for (int q = 0; q < IT / 4; q++) {
            float4 xlp = __ldg((const float4*)(lp  + ib) + q);
            float4 xol = __ldg((const float4*)(olp + ib) + q);
            float4 xv  = __ldg((const float4*)(val + ib) + q);
            float4 xnv = __ldg((const float4*)(nval + ib) + q);
            float4 xr  = __ldg((const float4*)(rew + ib) + q);
            float4 xt  = __ldg((const float4*)(term + ib) + q);
            const float* plp = (const float*)&xlp;
            const float* pol = (const float*)&xol;
            const float* pv  = (const float*)&xv;
            const float* pnv = (const float*)&xnv;
            const float* pr  = (const float*)&xr;
            const float* pt  = (const float*)&xt;
            #pragma unroll
            for (int c = 0; c < 4; c++) {
                int k = q * 4 + c;
                float ratio = expf(plp[c] - pol[c]);
                float rho   = fminf(1.0f, ratio);
                float td    = pr[c] + pt[c] * pnv[c];
                d[k] = rho * (td - pv[c]);
                a[k] = pt[c] * rho;
            }
        }
    } else {
        #pragma unroll
        for (int k = 0; k < IT; k++) {
            long long idx = ib + k;
            if (idx >= 0 && idx < (long long)n) {
                float ratio = expf(lp[idx] - olp[idx]);
                float rho   = fminf(1.0f, ratio);
                float td    = rew[idx] + term[idx] * nval[idx];
                d[k] = rho * (td - val[idx]);
                a[k] = term[idx] * rho;
            } else if (idx >= (long long)n) {
                a[k] = 0.0f; d[k] = 0.0f;   // right of array end: force y -> 0
            } else {
                a[k] = 1.0f; d[k] = 0.0f;   // left of array start: identity
            }
        }
    }

    // Thread-local composition (right-to-left): C(y) = f_0(f_1(...f_{IT-1}(y)))
    float A = 1.0f, B = 0.0f;
    #pragma unroll
    for (int k = IT - 1; k >= 0; k--) {
        B = a[k] * B + d[k];
        A = a[k] * A;
    }

    // Block inclusive scan over j (composition: inclusive[j] = f_j o ... o f_0)
    sA[j] = A; sB[j] = B;
    __syncthreads();
    #pragma unroll
    for (int o = 1; o < BT; o <<= 1) {
        float selfA = sA[j], selfB = sB[j];
        float pA = 1.0f, pB = 0.0f;
        if (j >= o) { pA = sA[j - o]; pB = sB[j - o]; }
        __syncthreads();
        sA[j] = selfA * pA;
        sB[j] = selfA * pB + selfB;
        __syncthreads();
    }

    // Thread 0 (j == BT-1) holds the block aggregate: publish + lookback.
    if (tid == 0) {
        float Ab = sA[BT - 1], Bb = sB[BT - 1];
        __stcg(&g_aggA[t], Ab);
        __stcg(&g_aggB[t], Bb);
        __threadfence();
        atomicExch(&g_flags[t], 1);

        float cA = 1.0f, cB = 0.0f;       // carry = composition of tiles t-1 .. 0
        int k = t - 1;
        while (k >= 0) {
            int f;
            do { f = *((volatile int*)&g_flags[k]); } while (f == 0);
            __threadfence();
            if (f == 2) {
                float pA = __ldcg(&g_preA[k]);
                float pB = __ldcg(&g_preB[k]);
                cB = cA * pB + cB;
                cA = cA * pA;
                break;
            } else {
                float xA = __ldcg(&g_aggA[k]);
                float xB = __ldcg(&g_aggB[k]);
                cB = cA * xB + cB;
                cA = cA * xA;
                k--;
            }
        }
        // inclusive prefix of this tile = Agg_t o carry
        float PA = Ab * cA;
        float PB = Ab * cB + Bb;
        __stcg(&g_preA[t], PA);
        __stcg(&g_preB[t], PB);
        __threadfence();
        atomicExch(&g_flags[t], 2);
        s_yR = cB;                         // incoming y at tile right edge (y_init = 0)
    }
    __syncthreads();

    // Exclusive prefix for this thread = inclusive[j-1] (identity for j == 0)
    float eA = 1.0f, eB = 0.0f;
    if (j > 0) { eA = sA[j - 1]; eB = sB[j - 1]; }
    float y = eA * s_yR + eB;              // y entering this thread's segment from the right

    float acc = 0.0f;
    if (full) {
        #pragma unroll
        for (int k = IT - 1; k >= 0; k--) {
            y = a[k] * y + d[k];
            out_pg[ib + k] = y;
            acc += y * y;
        }
    } else {
        #pragma unroll
        for (int k = IT - 1; k >= 0; k--) {
            y = a[k] * y + d[k];
            long long idx = ib + k;
            if (idx >= 0 && idx < (long long)n) {
                out_pg[idx] = y;
                acc += y * y;
            }
        }
    }

    // Deterministic per-tile loss partial
    __syncthreads();                       // sA/sB reads above are done
    sA[tid] = acc;
    __syncthreads();
    #pragma unroll
    for (int o = BT / 2; o > 0; o >>= 1) {
        if (tid < o) sA[tid] += sA[tid + o];
        __syncthreads();
    }
    if (tid == 0) g_partial[t] = sA[0];
}

__global__ void vtrace_finalize(float* __restrict__ out_loss, int n, int ntiles) {
    __shared__ float s[1024];
    int tid = threadIdx.x;
    float v = 0.0f;
    for (int i = tid; i < ntiles; i += 1024) v += g_partial[i];
    s[tid] = v;
    __syncthreads();
    #pragma unroll
    for (int o = 512; o > 0; o >>= 1) {
        if (tid < o) s[tid] += s[tid + o];
        __syncthreads();
    }
    if (tid == 0) out_loss[0] = s[0] / (float)n;
}

extern "C" void kernel_launch(void* const* d_in, const int* in_sizes, int n_in,
                              void* d_out, int out_size) {
    const float* lp   = (const float*)d_in[0];
    const float* olp  = (const float*)d_in[1];
    const float* val  = (const float*)d_in[2];
    const float* nval = (const float*)d_in[3];
    const float* rew  = (const float*)d_in[4];
    const float* term = (const float*)d_in[5];
    float* outf = (float*)d_out;

    int n = in_sizes[0];
    int ntiles = (n + TILE - 1) / TILE;

    // Output layout: [critic_loss, pg_advantages...] (out_size == n + 1).
    // Hedge: if out_size == n, there is no scalar slot.
    float* out_pg = (out_size > n) ? (outf + 1) : outf;

    vtrace_init<<<(ntiles + 255) / 256, 256>>>(ntiles);
    vtrace_scan<<<ntiles, BT>>>(lp, olp, val, nval, rew, term, out_pg, n, ntiles);
    if (out_size > n) {
        vtrace_finalize<<<1, 1024>>>(outf, n, ntiles);
    }
}

// round 3
// speedup vs baseline: 2.2816x; 2.2816x over previous
#include <cuda_runtime.h>

// V-trace, clip constants all 1.0 => rhos == cs == pg-clip == min(1, ratio).
// pg_advantages[i] == ys[i] (reverse scan output); critic_loss == mean(ys^2).
//
// Key numerics: a[i] = terminals[i]*rho[i] <= 0.99, so a tile's A-aggregate is
// <= 0.99^4096 ~ 1e-18 — below fp32 eps of any output. Cross-tile carry is
// exactly (in fp32) the right-neighbor tile's B aggregate. One-step lookback.
//
// Single fused kernel: epoch-tagged 64-bit publish word (no init kernel, no
// fence needed on the carry path — single-word atomicity), last-block-done
// loss reduction (no finalize kernel). Deterministic: fixed-order reductions,
// no atomics in the data path.
//
// NOTE: out_pg = d_out + 1 is only 4-byte aligned -> output stores MUST be
// scalar (misaligned-address trap with float4). Inputs are 16B-aligned.

#define BT 256
#define IT 16
#define TILE (BT * IT)
#define MAXTILES 4096
#define NWARP (BT / 32)

__device__ unsigned long long g_ticket;           // never reset; epoch = ticket/ntiles
__device__ unsigned long long g_done;             // never reset
__device__ unsigned long long g_pack[MAXTILES];   // (epoch)<<32 | f32bits(B_tile)
__device__ float              g_partial[MAXTILES];

__global__ __launch_bounds__(BT) void vtrace_fused(
    const float* __restrict__ lp,  const float* __restrict__ olp,
    const float* __restrict__ val, const float* __restrict__ nval,
    const float* __restrict__ rew, const float* __restrict__ term,
    float* __restrict__ out_pg, float* __restrict__ out_loss,
    int n, int ntiles, int has_loss)
{
    __shared__ unsigned long long s_ticket;
    __shared__ float s_wA[NWARP], s_wB[NWARP];
    __shared__ float s_cwA[NWARP], s_cwB[NWARP];
    __shared__ float s_carry;
    __shared__ float s_red[BT];

    const int tid  = threadIdx.x;
    const int lane = tid & 31;
    const int warp = tid >> 5;

    if (tid == 0) s_ticket = atomicAdd(&g_ticket, 1ULL);
    __syncthreads();
    const unsigned long long ticket = s_ticket;
    const int t = (int)(ticket % (unsigned long long)ntiles);   // t=0 is RIGHTMOST tile
    const unsigned epoch = (unsigned)(ticket / (unsigned long long)ntiles) + 1u;

    // Thread tid handles the tid-th IT-segment from the RIGHT edge of the tile.
    const long long tileR = (long long)n - (long long)t * TILE;          // exclusive right
    const long long ib    = tileR - (long long)(tid + 1) * IT;           // leftmost item

    float a[IT], d[IT];
    const bool full = (ib >= 0);   // right side never overruns by construction

    if (full) {
        #pragma unroll
        for (int q = 0; q < IT / 4; q++) {
            float4 xlp = __ldg((const float4*)(lp  + ib) + q);
            float4 xol = __ldg((const float4*)(olp + ib) + q);
            float4 xv  = __ldg((const float4*)(val + ib) + q);
            float4 xnv = __ldg((const float4*)(nval + ib) + q);
            float4 xr  = __ldg((const float4*)(rew + ib) + q);
            float4 xt  = __ldg((const float4*)(term + ib) + q);
            const float* plp = (const float*)&xlp;
            const float* pol = (const float*)&xol;
            const float* pv  = (const float*)&xv;
            const float* pnv = (const float*)&xnv;
            const float* pr  = (const float*)&xr;
            const float* pt  = (const float*)&xt;
            #pragma unroll
            for (int c = 0; c < 4; c++) {
                int k = q * 4 + c;
                float ratio = expf(plp[c] - pol[c]);
                float rho   = fminf(1.0f, ratio);
                float td    = pr[c] + pt[c] * pnv[c];
                d[k] = rho * (td - pv[c]);
                a[k] = pt[c] * rho;
            }
        }
    } else {
        #pragma unroll
        for (int k = 0; k < IT; k++) {
            long long idx = ib + k;
            if (idx >= 0 && idx < (long long)n) {
                float ratio = expf(lp[idx] - olp[idx]);
                float rho   = fminf(1.0f, ratio);
                float td    = rew[idx] + term[idx] * nval[idx];
                d[k] = rho * (td - val[idx]);
                a[k] = term[idx] * rho;
            } else if (idx < 0) {
                a[k] = 1.0f; d[k] = 0.0f;   // identity (left of array)
            } else {
                a[k] = 0.0f; d[k] = 0.0f;   // force y -> 0 (right of array)
            }
        }
    }

    // Thread-local composition right-to-left: (A, B) with y_out = A*y_in + B
    float A = 1.0f, B = 0.0f;
    #pragma unroll
    for (int k = IT - 1; k >= 0; k--) {
        B = a[k] * B + d[k];
        A = a[k] * A;
    }

    // Warp-level inclusive scan over ascending lane (lane 0 = rightmost segment).
    #pragma unroll
    for (int o = 1; o < 32; o <<= 1) {
        float pA = __shfl_up_sync(0xFFFFFFFFu, A, o);
        float pB = __shfl_up_sync(0xFFFFFFFFu, B, o);
        if (lane >= o) {
            B = A * pB + B;    // self ∘ prev
            A = A * pA;
        }
    }
    // Warp-internal exclusive (from lane-1's inclusive).
    float eA = __shfl_up_sync(0xFFFFFFFFu, A, 1);
    float eB = __shfl_up_sync(0xFFFFFFFFu, B, 1);
    if (lane == 0) { eA = 1.0f; eB = 0.0f; }

    if (lane == 31) { s_wA[warp] = A; s_wB[warp] = B; }
    __syncthreads();

    // Thread 0: serial exclusive scan over 8 warp aggregates, publish + poll.
    if (tid == 0) {
        float cA = 1.0f, cB = 0.0f;
        #pragma unroll
        for (int w = 0; w < NWARP; w++) {
            s_cwA[w] = cA; s_cwB[w] = cB;
            float wa = s_wA[w], wb = s_wB[w];
            cB = wa * cB + wb;     // agg_w ∘ carry
            cA = wa * cA;
        }
        // (cA, cB) = full tile aggregate. cA <= 0.99^4096: publish only B.
        unsigned long long mine =
            ((unsigned long long)epoch << 32) | (unsigned long long)__float_as_uint(cB);
        atomicExch(&g_pack[t], mine);

        float carry = 0.0f;
        if (t > 0) {
            unsigned long long v;
            do {
                v = *((volatile unsigned long long*)&g_pack[t - 1]);
            } while ((unsigned)(v >> 32) != epoch);
            carry = __uint_as_float((unsigned)v);
        }
        s_carry = carry;
    }
    __syncthreads();

    // Incoming y for this thread's segment (entering from the right):
    const float cwA = s_cwA[warp], cwB = s_cwB[warp];
    float EA = eA * cwA;
    float EB = eA * cwB + eB;
    float y = EA * s_carry + EB;

    float acc = 0.0f;
    if (full) {
        #pragma unroll
        for (int k = IT - 1; k >= 0; k--) {
            y = a[k] * y + d[k];
            out_pg[ib + k] = y;       // scalar store: out_pg may be 4B-aligned only
            acc += y * y;
        }
    } else {
        #pragma unroll
        for (int k = IT - 1; k >= 0; k--) {
            y = a[k] * y + d[k];
            long long idx = ib + k;
            if (idx >= 0 && idx < (long long)n) {
                out_pg[idx] = y;
                acc += y * y;
            }
        }
    }

    if (!has_loss) return;

    // Deterministic per-tile loss partial (fixed-order block reduction).
    s_red[tid] = acc;
    __syncthreads();
    #pragma unroll
    for (int o = BT / 2; o > 0; o >>= 1) {
        if (tid < o) s_red[tid] += s_red[tid + o];
        __syncthreads();
    }

    if (tid == 0) {
        __stcg(&g_partial[t], s_red[0]);
        __threadfence();
        unsigned long long old = atomicAdd(&g_done, 1ULL);
        s_ticket = ((old % (unsigned long long)ntiles) ==
                    (unsigned long long)(ntiles - 1)) ? 1ULL : 0ULL;
    }
    __syncthreads();

    if (s_ticket) {  // last block of this replay: reduce partials, fixed order
        __threadfence();
        float v = 0.0f;
        for (int i = tid; i < ntiles; i += BT) v += __ldcg(&g_partial[i]);
        s_red[tid] = v;
        __syncthreads();
        #pragma unroll
        for (int o = BT / 2; o > 0; o >>= 1) {
            if (tid < o) s_red[tid] += s_red[tid + o];
            __syncthreads();
        }
        if (tid == 0) out_loss[0] = s_red[0] / (float)n;
    }
}

extern "C" void kernel_launch(void* const* d_in, const int* in_sizes, int n_in,
                              void* d_out, int out_size) {
    const float* lp   = (const float*)d_in[0];
    const float* olp  = (const float*)d_in[1];
    const float* val  = (const float*)d_in[2];
    const float* nval = (const float*)d_in[3];
    const float* rew  = (const float*)d_in[4];
    const float* term = (const float*)d_in[5];
    float* outf = (float*)d_out;

    int n = in_sizes[0];
    int ntiles = (n + TILE - 1) / TILE;

    // Output layout: [critic_loss, pg_advantages...] when out_size == n + 1.
    int has_loss = (out_size > n) ? 1 : 0;
    float* out_pg = has_loss ? (outf + 1) : outf;

    vtrace_fused<<<ntiles, BT>>>(lp, olp, val, nval, rew, term,
                                 out_pg, outf, n, ntiles, has_loss);
}